// round 1
// baseline (speedup 1.0000x reference)
#include <cuda_runtime.h>
#include <math.h>

// Problem constants
#define NOBJ 2048
#define FDIM 2048
#define HDIM 1024
#define GDIM 6144   // 6*H
#define SENT 2048   // sentinel "no child" row index

// ---------------- scratch (device globals; no allocation allowed) -----------
__device__ float g_wT_x[FDIM * GDIM];     // w_ioffux^T   [K=2048][N=6144]
__device__ float g_wT_px[FDIM * HDIM];    // w_px^T       [K=2048][N=1024]
__device__ float g_wT_rec[FDIM * GDIM];   // [w_l; w_r]^T [K=2048][N=6144]
__device__ float g_xg[NOBJ * GDIM];       // x_gates
__device__ float g_px[NOBJ * HDIM];       // px (no bias)
__device__ float g_c[(NOBJ + 1) * HDIM];  // cell states (+ sentinel zero row)
__device__ float g_h[(NOBJ + 1) * HDIM];  // hidden states (+ sentinel zero row)
__device__ float g_gates[512 * GDIM];     // per-level GEMM output (M<=512)
__device__ float g_part[32 * 8 * GDIM];   // small-level k-split partials

__device__ __forceinline__ float sigf(float x) { return 1.0f / (1.0f + expf(-x)); }

// ---------------- zero sentinel rows ----------------------------------------
__global__ void zero_sent_k() {
    int j = blockIdx.x * 256 + threadIdx.x;
    if (j < HDIM) {
        g_c[(size_t)SENT * HDIM + j] = 0.0f;
        g_h[(size_t)SENT * HDIM + j] = 0.0f;
    }
}

// ---------------- transpose: src[rows][cols] -> dst[(c+off)*ld + r] ---------
// which: 0 = g_wT_x, 1 = g_wT_px, 2 = g_wT_rec
__global__ void transpose_k(const float* __restrict__ src, int srcCols,
                            int which, int dstLD, int dstOff) {
    __shared__ float tile[32][33];
    float* dst = (which == 0) ? g_wT_x : (which == 1) ? g_wT_px : g_wT_rec;
    int c0 = blockIdx.x * 32, r0 = blockIdx.y * 32;
#pragma unroll
    for (int i = 0; i < 32; i += 8)
        tile[threadIdx.y + i][threadIdx.x] =
            src[(size_t)(r0 + threadIdx.y + i) * srcCols + c0 + threadIdx.x];
    __syncthreads();
#pragma unroll
    for (int i = 0; i < 32; i += 8)
        dst[(size_t)(c0 + threadIdx.y + i + dstOff) * dstLD + r0 + threadIdx.x] =
            tile[threadIdx.x][threadIdx.y + i];
}

// ---------------- fp32 SIMT GEMM: C[M,N] = A[M,K] * B[K,N] ------------------
// BM=128, BN=64, BK=16, 256 threads, 8x4 micro-tile.
// gather==0: A is a plain row-major pointer (M divisible by 128).
// gather==1: logical A row r = concat(h[left(base+r)], h[right(base+r)]);
//            padded rows (r>=M) read the sentinel zero row.
// whichB: 0 = g_wT_x, 1 = g_wT_px, 2 = g_wT_rec ; whichC: 0 = g_xg, 1 = g_px, 2 = g_gates
__global__ __launch_bounds__(256) void gemm_k(const float* __restrict__ A,
                                              int whichB, int whichC,
                                              int M, int N, int K,
                                              int gather, int base) {
    __shared__ float As[16][128];
    __shared__ float Bs[16][64];
    const float* B = (whichB == 0) ? g_wT_x : (whichB == 1) ? g_wT_px : g_wT_rec;
    float* C = (whichC == 0) ? g_xg : (whichC == 1) ? g_px : g_gates;

    const int tid = threadIdx.x;
    const int tx = tid & 15, ty = tid >> 4;
    const int rowBlock = blockIdx.y * 128;
    const int colBlock = blockIdx.x * 64;

    float acc[8][4];
#pragma unroll
    for (int i = 0; i < 8; i++)
#pragma unroll
        for (int j = 0; j < 4; j++) acc[i][j] = 0.0f;

    for (int k0 = 0; k0 < K; k0 += 16) {
        // A tile: 128 x 16 (512 float4, 2 per thread), stored transposed As[k][m]
#pragma unroll
        for (int i = 0; i < 2; i++) {
            int id = tid * 2 + i;
            int r = id >> 2, kq = (id & 3) << 2;
            const float* src;
            if (!gather) {
                src = A + (size_t)(rowBlock + r) * K + k0 + kq;
            } else {
                int rg = rowBlock + r;
                int child = SENT;
                if (rg < M) {
                    int node = base + rg;
                    child = (k0 < HDIM) ? (2 * node + 1) : (2 * node + 2);
                    if (child >= NOBJ) child = SENT;
                }
                src = g_h + (size_t)child * HDIM + ((k0 & (HDIM - 1)) + kq);
            }
            float4 v = *(const float4*)src;
            As[kq + 0][r] = v.x; As[kq + 1][r] = v.y;
            As[kq + 2][r] = v.z; As[kq + 3][r] = v.w;
        }
        // B tile: 16 x 64 (256 float4, 1 per thread)
        {
            int kk = tid >> 4, nq = (tid & 15) << 2;
            float4 v = *(const float4*)(B + (size_t)(k0 + kk) * N + colBlock + nq);
            *(float4*)&Bs[kk][nq] = v;
        }
        __syncthreads();
#pragma unroll
        for (int kk = 0; kk < 16; kk++) {
            float a[8], b[4];
            *(float4*)&a[0] = *(const float4*)&As[kk][ty * 8];
            *(float4*)&a[4] = *(const float4*)&As[kk][ty * 8 + 4];
            *(float4*)&b[0] = *(const float4*)&Bs[kk][tx * 4];
#pragma unroll
            for (int i = 0; i < 8; i++)
#pragma unroll
                for (int j = 0; j < 4; j++) acc[i][j] += a[i] * b[j];
        }
        __syncthreads();
    }
#pragma unroll
    for (int i = 0; i < 8; i++) {
        int row = rowBlock + ty * 8 + i;
        if (row < M) {
            float4 v = make_float4(acc[i][0], acc[i][1], acc[i][2], acc[i][3]);
            *(float4*)(C + (size_t)row * N + colBlock + tx * 4) = v;
        }
    }
}

// ---------------- small-level GEMV (M <= 32 nodes), K-split by 8 -------------
// grid = (96 n-tiles of 64, 8 k-chunks of 256), 64 threads.
// partial[(m*8 + kc)*6144 + n] = sum_k hs[m][k] * Wrec^T[kc*256+k][n]
template <int M>
__global__ void gemv_k(int base) {
    __shared__ float hs[M][256];
    const int tid = threadIdx.x;  // 64
    const int kc = blockIdx.y;
    const int kbase = kc * 256;
    for (int idx = tid; idx < M * 64; idx += 64) {
        int m = idx >> 6;
        int o = (idx & 63) << 2;
        int node = base + m;
        int child = (kbase < HDIM) ? (2 * node + 1) : (2 * node + 2);
        if (child >= NOBJ) child = SENT;
        float4 v = *(const float4*)(g_h + (size_t)child * HDIM +
                                    ((kbase & (HDIM - 1)) + o));
        *(float4*)&hs[m][o] = v;
    }
    __syncthreads();
    int n = blockIdx.x * 64 + tid;
    float acc[M];
#pragma unroll
    for (int m = 0; m < M; m++) acc[m] = 0.0f;
    const float* w = g_wT_rec + (size_t)kbase * GDIM + n;
#pragma unroll 4
    for (int k = 0; k < 256; k++) {
        float wv = w[(size_t)k * GDIM];
#pragma unroll
        for (int m = 0; m < M; m++) acc[m] += hs[m][k] * wv;
    }
#pragma unroll
    for (int m = 0; m < M; m++)
        g_part[((size_t)m * 8 + kc) * GDIM + n] = acc[m];
}

// ---------------- fused elementwise (gates -> c, h, h_final) -----------------
// mode: 0 = leaves (no h-term), 1 = read g_gates, 2 = sum 8 k-split partials
__global__ void ew_k(int base, int mode, float* __restrict__ out,
                     const float* __restrict__ b_x, const float* __restrict__ b_l,
                     const float* __restrict__ b_r, const float* __restrict__ b_px) {
    int r = blockIdx.x;
    int j = blockIdx.y * 256 + threadIdx.x;
    int i = base + r;

    float g[6];
#pragma unroll
    for (int s = 0; s < 6; s++) {
        int k = s * HDIM + j;
        float v = g_xg[(size_t)i * GDIM + k] + b_x[k] + b_l[k] + b_r[k];
        if (mode == 1) {
            v += g_gates[(size_t)r * GDIM + k];
        } else if (mode == 2) {
#pragma unroll
            for (int p = 0; p < 8; p++) v += g_part[((size_t)r * 8 + p) * GDIM + k];
        }
        g[s] = v;
    }
    int lc = 2 * i + 1; if (lc >= NOBJ) lc = SENT;
    int rc = 2 * i + 2; if (rc >= NOBJ) rc = SENT;
    float cl = g_c[(size_t)lc * HDIM + j];
    float cr = g_c[(size_t)rc * HDIM + j];

    float ig = sigf(g[0]), og = sigf(g[1]);
    float fl = sigf(g[2]), fr = sigf(g[3]);
    float u = tanhf(g[4]), rr = sigf(g[5]);

    float c = ig * u + fl * cl + fr * cr;
    float h = og * tanhf(c);
    float px = g_px[(size_t)i * HDIM + j] + b_px[j];
    float hf = rr * h + (1.0f - rr) * px;

    g_c[(size_t)i * HDIM + j] = c;
    g_h[(size_t)i * HDIM + j] = hf;
    out[(size_t)i * HDIM + j] = hf;
}

// ---------------- launcher ---------------------------------------------------
extern "C" void kernel_launch(void* const* d_in, const int* in_sizes, int n_in,
                              void* d_out, int out_size) {
    const float* features = (const float*)d_in[0];
    const float* w_x  = (const float*)d_in[1];
    const float* b_x  = (const float*)d_in[2];
    const float* w_l  = (const float*)d_in[3];
    const float* b_l  = (const float*)d_in[4];
    const float* w_r  = (const float*)d_in[5];
    const float* b_r  = (const float*)d_in[6];
    const float* w_px = (const float*)d_in[7];
    const float* b_px = (const float*)d_in[8];
    float* out = (float*)d_out;

    zero_sent_k<<<4, 256>>>();

    dim3 tb(32, 8);
    // w_ioffux [6144,2048] -> g_wT_x [2048][6144]
    transpose_k<<<dim3(FDIM / 32, GDIM / 32), tb>>>(w_x, FDIM, 0, GDIM, 0);
    // w_px [1024,2048] -> g_wT_px [2048][1024]
    transpose_k<<<dim3(FDIM / 32, HDIM / 32), tb>>>(w_px, FDIM, 1, HDIM, 0);
    // w_l [6144,1024] -> g_wT_rec rows [0,1024)
    transpose_k<<<dim3(HDIM / 32, GDIM / 32), tb>>>(w_l, HDIM, 2, GDIM, 0);
    // w_r [6144,1024] -> g_wT_rec rows [1024,2048)
    transpose_k<<<dim3(HDIM / 32, GDIM / 32), tb>>>(w_r, HDIM, 2, GDIM, 1024);

    // Batched input projections
    gemm_k<<<dim3(GDIM / 64, NOBJ / 128), 256>>>(features, 0, 0, NOBJ, GDIM, FDIM, 0, 0);
    gemm_k<<<dim3(HDIM / 64, NOBJ / 128), 256>>>(features, 1, 1, NOBJ, HDIM, FDIM, 0, 0);

    // Leaves: nodes 1024..2047 (children are all sentinel => no GEMM)
    ew_k<<<dim3(1024, HDIM / 256), 256>>>(1024, 0, out, b_x, b_l, b_r, b_px);

    // Node 1023 (only internal node at level 10; left child = 2047)
    gemv_k<1><<<dim3(GDIM / 64, 8), 64>>>(1023);
    ew_k<<<dim3(1, HDIM / 256), 256>>>(1023, 2, out, b_x, b_l, b_r, b_px);

    // Levels 9..0
    for (int l = 9; l >= 0; l--) {
        int base = (1 << l) - 1;
        int M = 1 << l;
        if (M >= 64) {
            gemm_k<<<dim3(GDIM / 64, (M + 127) / 128), 256>>>(nullptr, 2, 2, M, GDIM, FDIM, 1, base);
            ew_k<<<dim3(M, HDIM / 256), 256>>>(base, 1, out, b_x, b_l, b_r, b_px);
        } else {
            dim3 gg(GDIM / 64, 8);
            switch (M) {
                case 32: gemv_k<32><<<gg, 64>>>(base); break;
                case 16: gemv_k<16><<<gg, 64>>>(base); break;
                case 8:  gemv_k<8><<<gg, 64>>>(base); break;
                case 4:  gemv_k<4><<<gg, 64>>>(base); break;
                case 2:  gemv_k<2><<<gg, 64>>>(base); break;
                case 1:  gemv_k<1><<<gg, 64>>>(base); break;
            }
            ew_k<<<dim3(M, HDIM / 256), 256>>>(base, 2, out, b_x, b_l, b_r, b_px);
        }
    }
}

// round 7
// speedup vs baseline: 1.5314x; 1.5314x over previous
#include <cuda_runtime.h>
#include <cuda_bf16.h>
#include <math.h>
#include <stdint.h>

// ----------------------------- problem constants ----------------------------
#define NOBJ 2048
#define FDIM 2048
#define HDIM 1024
#define GDIM 6144
#define XG_LD 7168          // 6H gates + H px concatenated
#define EITER 192           // 3 products x (2048/32) k-chunks

// ----------------------------- device globals (no allocs) -------------------
__device__ __align__(1024) __nv_bfloat16 g_feat_hi[NOBJ * FDIM];
__device__ __align__(1024) __nv_bfloat16 g_feat_lo[NOBJ * FDIM];
__device__ __align__(1024) __nv_bfloat16 g_wb_hi[(size_t)XG_LD * FDIM];   // [w_x ; w_px]
__device__ __align__(1024) __nv_bfloat16 g_wb_lo[(size_t)XG_LD * FDIM];
__device__ __align__(1024) __nv_bfloat16 g_wrec_hi[(size_t)GDIM * FDIM];  // row n = [w_l[n]|w_r[n]]
__device__ __align__(1024) __nv_bfloat16 g_wrec_lo[(size_t)GDIM * FDIM];
__device__ __align__(1024) __nv_bfloat16 g_hrec_hi[NOBJ * FDIM];          // row p = [h(2p+1)|h(2p+2)]
__device__ __align__(1024) __nv_bfloat16 g_hrec_lo[NOBJ * FDIM];
__device__ float g_xgpx[(size_t)NOBJ * XG_LD];
__device__ float g_gates[512 * GDIM];
__device__ float g_gatesT[GDIM * 64];
__device__ float g_c[NOBJ * HDIM];

// ----------------------------- asm helpers ----------------------------------
__device__ __forceinline__ uint32_t smem_u32(const void* p) {
    uint32_t a;
    asm("{ .reg .u64 t; cvta.to.shared.u64 t, %1; cvt.u32.u64 %0, t; }" : "=r"(a) : "l"(p));
    return a;
}
__device__ __forceinline__ void cp16(uint32_t dst, const void* src, int srcsize) {
    asm volatile("cp.async.cg.shared.global [%0], [%1], 16, %2;"
                 :: "r"(dst), "l"(src), "r"(srcsize) : "memory");
}
#define CP_COMMIT() asm volatile("cp.async.commit_group;" ::: "memory")
#define CP_WAIT1() asm volatile("cp.async.wait_group 1;" ::: "memory")
#define CP_WAIT0() asm volatile("cp.async.wait_group 0;" ::: "memory")

__device__ __forceinline__ void ldsm_x4(uint32_t* r, uint32_t addr) {
    asm volatile("ldmatrix.sync.aligned.m8n8.x4.shared.b16 {%0,%1,%2,%3}, [%4];"
                 : "=r"(r[0]), "=r"(r[1]), "=r"(r[2]), "=r"(r[3]) : "r"(addr));
}
__device__ __forceinline__ void mma16816(float* c, const uint32_t* a, const uint32_t* b) {
    asm volatile(
        "mma.sync.aligned.m16n8k16.row.col.f32.bf16.bf16.f32 "
        "{%0,%1,%2,%3}, {%4,%5,%6,%7}, {%8,%9}, {%0,%1,%2,%3};"
        : "+f"(c[0]), "+f"(c[1]), "+f"(c[2]), "+f"(c[3])
        : "r"(a[0]), "r"(a[1]), "r"(a[2]), "r"(a[3]), "r"(b[0]), "r"(b[1]));
}

// ----------------------------- bf16 hi/lo TN GEMM ---------------------------
// C[M,N] = A[M,2048] @ B[N,2048]^T with 3-product hi/lo split:
//   phases: Ah*Bh, Al*Bh, Ah*Bl  (effective K = 6144)
// grid: (N/BN, M/BM). 256 threads, 2x4 warps. B rows >= nB zero-filled.
template <int BM, int BN>
__global__ __launch_bounds__(256, 1)
void gemm_bf16(const __nv_bfloat16* __restrict__ Ahi, const __nv_bfloat16* __restrict__ Alo,
               const __nv_bfloat16* __restrict__ Bhi, const __nv_bfloat16* __restrict__ Blo,
               float* __restrict__ C, int ldc, int nB) {
    constexpr int TH = 256;
    constexpr int WM = BM / 2, WN = BN / 4;
    constexpr int MT = WM / 16, NT = WN / 8;
    constexpr int PITCH = 80;                 // 64B row + 16B skew
    constexpr int SA = BM * PITCH, SB = BN * PITCH, STG = SA + SB;

    extern __shared__ char smem[];
    const uint32_t sbase = smem_u32(smem);
    const int tid = threadIdx.x, lane = tid & 31, wid = tid >> 5;
    const int wm = wid >> 2, wn = wid & 3;

    const int rowA0 = blockIdx.y * BM;
    const int rowB0 = blockIdx.x * BN;

    float acc[MT][NT][4];
#pragma unroll
    for (int i = 0; i < MT; i++)
#pragma unroll
        for (int j = 0; j < NT; j++)
#pragma unroll
            for (int t = 0; t < 4; t++) acc[i][j][t] = 0.0f;

    auto issue = [&](int e, int s) {
        const int p = e >> 6;
        const int k0 = (e & 63) * 32;
        const __nv_bfloat16* pa = (p == 1) ? Alo : Ahi;
        const __nv_bfloat16* pb = (p == 2) ? Blo : Bhi;
        const uint32_t sA = sbase + s * STG, sB = sA + SA;
#pragma unroll
        for (int idx = tid; idx < BM * 4; idx += TH) {
            int r = idx >> 2, sg = idx & 3;
            cp16(sA + r * PITCH + sg * 16,
                 pa + (size_t)(rowA0 + r) * FDIM + k0 + sg * 8, 16);
        }
#pragma unroll
        for (int idx = tid; idx < BN * 4; idx += TH) {
            int r = idx >> 2, sg = idx & 3;
            int gr = rowB0 + r;
            cp16(sB + r * PITCH + sg * 16,
                 pb + (size_t)gr * FDIM + k0 + sg * 8, gr < nB ? 16 : 0);
        }
    };

    issue(0, 0); CP_COMMIT();
    issue(1, 1); CP_COMMIT();

    for (int e = 0; e < EITER; e++) {
        if (e + 1 < EITER) CP_WAIT1(); else CP_WAIT0();
        __syncthreads();
        if (e + 2 < EITER) { issue(e + 2, (e + 2) % 3); CP_COMMIT(); }

        const int s = e % 3;
        const uint32_t sA = sbase + s * STG, sB = sA + SA;
        const uint32_t aBase = sA + (wm * WM + (lane & 15)) * PITCH + (lane >> 4) * 16;
        const uint32_t bBase = sB + (wn * WN + ((lane >> 4) * 8) + (lane & 7)) * PITCH +
                               ((lane >> 3) & 1) * 16;
#pragma unroll
        for (int kk = 0; kk < 2; kk++) {
            uint32_t a[MT][4];
#pragma unroll
            for (int i = 0; i < MT; i++)
                ldsm_x4(a[i], aBase + i * 16 * PITCH + kk * 32);
            uint32_t b[NT][2];
#pragma unroll
            for (int jj = 0; jj < NT / 2; jj++) {
                uint32_t r4[4];
                ldsm_x4(r4, bBase + jj * 16 * PITCH + kk * 32);
                b[2 * jj][0] = r4[0]; b[2 * jj][1] = r4[1];
                b[2 * jj + 1][0] = r4[2]; b[2 * jj + 1][1] = r4[3];
            }
#pragma unroll
            for (int i = 0; i < MT; i++)
#pragma unroll
                for (int j = 0; j < NT; j++) mma16816(acc[i][j], a[i], b[j]);
        }
    }

    // store
    const int mrow0 = blockIdx.y * BM + wm * WM + (lane >> 2);
    const int ncol0 = blockIdx.x * BN + wn * WN + (lane & 3) * 2;
#pragma unroll
    for (int i = 0; i < MT; i++)
#pragma unroll
        for (int j = 0; j < NT; j++) {
            int m = mrow0 + i * 16;
            int n = ncol0 + j * 8;
            *(float2*)(C + (size_t)m * ldc + n) = make_float2(acc[i][j][0], acc[i][j][1]);
            *(float2*)(C + (size_t)(m + 8) * ldc + n) = make_float2(acc[i][j][2], acc[i][j][3]);
        }
}

// ----------------------------- split fp32 -> bf16 hi/lo ---------------------
__global__ void split_k(const float* __restrict__ src, __nv_bfloat16* __restrict__ hi,
                        __nv_bfloat16* __restrict__ lo, int total, int scols,
                        int dld, int doff) {
    int idx = (blockIdx.x * 256 + threadIdx.x) * 4;
    if (idx >= total) return;
    float4 v = *(const float4*)(src + idx);
    int r = idx / scols, c = idx - r * scols;
    size_t d = (size_t)r * dld + doff + c;
    float x[4] = {v.x, v.y, v.z, v.w};
#pragma unroll
    for (int t = 0; t < 4; t++) {
        __nv_bfloat16 h = __float2bfloat16(x[t]);
        hi[d + t] = h;
        lo[d + t] = __float2bfloat16(x[t] - __bfloat162float(h));
    }
}

__global__ void zero_hrec_k() {  // node 1023 has no right child
    int j = threadIdx.x;
    g_hrec_hi[1023 * FDIM + 1024 + j] = __float2bfloat16(0.0f);
    g_hrec_lo[1023 * FDIM + 1024 + j] = __float2bfloat16(0.0f);
}

// ----------------------------- fused LSTM elementwise ------------------------
__device__ __forceinline__ float sigf(float x) { return 1.0f / (1.0f + expf(-x)); }

__device__ __forceinline__ void lstm_core(const float* g, float cl, float cr, float px,
                                          float& c, float& hf) {
    float ig = sigf(g[0]), og = sigf(g[1]);
    float fl = sigf(g[2]), fr = sigf(g[3]);
    float u = tanhf(g[4]), rr = sigf(g[5]);
    c = ig * u + fl * cl + fr * cr;
    float h = og * tanhf(c);
    hf = rr * h + (1.0f - rr) * px;
}

__device__ __forceinline__ void write_node(int i, int j, float c, float hf,
                                           float* __restrict__ out) {
    g_c[(size_t)i * HDIM + j] = c;
    out[(size_t)i * HDIM + j] = hf;
    if (i > 0) {
        int p = (i - 1) >> 1;
        int off = (i & 1) ? 0 : 1024;  // odd index = left child
        __nv_bfloat16 h = __float2bfloat16(hf);
        g_hrec_hi[(size_t)p * FDIM + off + j] = h;
        g_hrec_lo[(size_t)p * FDIM + off + j] = __float2bfloat16(hf - __bfloat162float(h));
    }
}

__global__ void ew_leaf(float* __restrict__ out, const float* __restrict__ bx,
                        const float* __restrict__ bl, const float* __restrict__ br,
                        const float* __restrict__ bpx) {
    int i = 1024 + blockIdx.x;
    int j = blockIdx.y * 256 + threadIdx.x;
    const float* xr = g_xgpx + (size_t)i * XG_LD;
    float g[6];
#pragma unroll
    for (int s = 0; s < 6; s++) {
        int k = s * HDIM + j;
        g[s] = xr[k] + bx[k] + bl[k] + br[k];
    }
    float px = xr[GDIM + j] + bpx[j];
    float c, hf;
    lstm_core(g, 0.0f, 0.0f, px, c, hf);
    write_node(i, j, c, hf, out);
}

__global__ void ew_big(int base, float* __restrict__ out, const float* __restrict__ bx,
                       const float* __restrict__ bl, const float* __restrict__ br,
                       const float* __restrict__ bpx) {
    int r = blockIdx.x;
    int i = base + r;
    int j = blockIdx.y * 256 + threadIdx.x;
    const float* xr = g_xgpx + (size_t)i * XG_LD;
    const float* gr = g_gates + (size_t)r * GDIM;
    float g[6];
#pragma unroll
    for (int s = 0; s < 6; s++) {
        int k = s * HDIM + j;
        g[s] = xr[k] + gr[k] + bx[k] + bl[k] + br[k];
    }
    int lc = 2 * i + 1, rc = 2 * i + 2;
    float cl = (lc < NOBJ) ? g_c[(size_t)lc * HDIM + j] : 0.0f;
    float cr = (rc < NOBJ) ? g_c[(size_t)rc * HDIM + j] : 0.0f;
    float px = xr[GDIM + j] + bpx[j];
    float c, hf;
    lstm_core(g, cl, cr, px, c, hf);
    write_node(i, j, c, hf, out);
}

__global__ void ew_small(int base, int M, float* __restrict__ out,
                         const float* __restrict__ bx, const float* __restrict__ bl,
                         const float* __restrict__ br, const float* __restrict__ bpx) {
    int r = blockIdx.x * 32 + threadIdx.x;
    int j = blockIdx.y * 8 + threadIdx.y;
    if (r >= M) return;
    int i = base + r;
    const float* xr = g_xgpx + (size_t)i * XG_LD;
    float g[6];
#pragma unroll
    for (int s = 0; s < 6; s++) {
        int k = s * HDIM + j;
        g[s] = xr[k] + g_gatesT[(size_t)k * 64 + r] + bx[k] + bl[k] + br[k];
    }
    int lc = 2 * i + 1, rc = 2 * i + 2;
    float cl = (lc < NOBJ) ? g_c[(size_t)lc * HDIM + j] : 0.0f;
    float cr = (rc < NOBJ) ? g_c[(size_t)rc * HDIM + j] : 0.0f;
    float px = xr[GDIM + j] + bpx[j];
    float c, hf;
    lstm_core(g, cl, cr, px, c, hf);
    write_node(i, j, c, hf, out);
}

// ----------------------------- host launcher ---------------------------------
extern "C" void kernel_launch(void* const* d_in, const int* in_sizes, int n_in,
                              void* d_out, int out_size) {
    const float* features = (const float*)d_in[0];
    const float* w_x  = (const float*)d_in[1];
    const float* b_x  = (const float*)d_in[2];
    const float* w_l  = (const float*)d_in[3];
    const float* b_l  = (const float*)d_in[4];
    const float* w_r  = (const float*)d_in[5];
    const float* b_r  = (const float*)d_in[6];
    const float* w_px = (const float*)d_in[7];
    const float* b_px = (const float*)d_in[8];
    float* out = (float*)d_out;

    void *pFh, *pFl, *pWh, *pWl, *pRh, *pRl, *pHh, *pHl, *pXG, *pG, *pGT;
    cudaGetSymbolAddress(&pFh, g_feat_hi); cudaGetSymbolAddress(&pFl, g_feat_lo);
    cudaGetSymbolAddress(&pWh, g_wb_hi);   cudaGetSymbolAddress(&pWl, g_wb_lo);
    cudaGetSymbolAddress(&pRh, g_wrec_hi); cudaGetSymbolAddress(&pRl, g_wrec_lo);
    cudaGetSymbolAddress(&pHh, g_hrec_hi); cudaGetSymbolAddress(&pHl, g_hrec_lo);
    cudaGetSymbolAddress(&pXG, g_xgpx);
    cudaGetSymbolAddress(&pG, g_gates);
    cudaGetSymbolAddress(&pGT, g_gatesT);

    __nv_bfloat16* fh = (__nv_bfloat16*)pFh; __nv_bfloat16* fl = (__nv_bfloat16*)pFl;
    __nv_bfloat16* wh = (__nv_bfloat16*)pWh; __nv_bfloat16* wl = (__nv_bfloat16*)pWl;
    __nv_bfloat16* rh = (__nv_bfloat16*)pRh; __nv_bfloat16* rl = (__nv_bfloat16*)pRl;
    __nv_bfloat16* hh = (__nv_bfloat16*)pHh; __nv_bfloat16* hl = (__nv_bfloat16*)pHl;

    // smem: 3 stages x (BM+BN) x 80B
    const int SMEM_BIG = 3 * (128 + 256) * 80;   // 92160
    const int SMEM_SML = 3 * (64 + 64) * 80;     // 30720
    cudaFuncSetAttribute(gemm_bf16<128, 256>, cudaFuncAttributeMaxDynamicSharedMemorySize, SMEM_BIG);
    cudaFuncSetAttribute(gemm_bf16<64, 64>, cudaFuncAttributeMaxDynamicSharedMemorySize, SMEM_SML);

    zero_hrec_k<<<1, 1024>>>();
    split_k<<<(NOBJ * FDIM / 4 + 255) / 256, 256>>>(features, fh, fl, NOBJ * FDIM, FDIM, FDIM, 0);
    split_k<<<(GDIM * FDIM / 4 + 255) / 256, 256>>>(w_x, wh, wl, GDIM * FDIM, FDIM, FDIM, 0);
    split_k<<<(HDIM * FDIM / 4 + 255) / 256, 256>>>(w_px, wh + (size_t)GDIM * FDIM,
                                                    wl + (size_t)GDIM * FDIM,
                                                    HDIM * FDIM, FDIM, FDIM, 0);
    split_k<<<(GDIM * HDIM / 4 + 255) / 256, 256>>>(w_l, rh, rl, GDIM * HDIM, HDIM, FDIM, 0);
    split_k<<<(GDIM * HDIM / 4 + 255) / 256, 256>>>(w_r, rh, rl, GDIM * HDIM, HDIM, FDIM, 1024);

    // fused input projections: [2048,7168] = features @ [w_x;w_px]^T
    gemm_bf16<128, 256><<<dim3(XG_LD / 256, NOBJ / 128), 256, SMEM_BIG>>>(
        fh, fl, wh, wl, (float*)pXG, XG_LD, XG_LD);

    // leaves: nodes 1024..2047
    ew_leaf<<<dim3(1024, HDIM / 256), 256>>>(out, b_x, b_l, b_r, b_px);

    // node 1023 (single internal node at level 10)
    gemm_bf16<64, 64><<<dim3(1, GDIM / 64), 256, SMEM_SML>>>(
        rh, rl, hh + (size_t)1023 * FDIM, hl + (size_t)1023 * FDIM, (float*)pGT, 64, 1);
    ew_small<<<dim3(1, HDIM / 8), dim3(32, 8)>>>(1023, 1, out, b_x, b_l, b_r, b_px);

    // levels 9..0
    for (int l = 9; l >= 0; l--) {
        int base = (1 << l) - 1;
        int M = 1 << l;
        if (M >= 128) {
            gemm_bf16<128, 256><<<dim3(GDIM / 256, M / 128), 256, SMEM_BIG>>>(
                hh + (size_t)base * FDIM, hl + (size_t)base * FDIM, rh, rl,
                (float*)pG, GDIM, GDIM);
            ew_big<<<dim3(M, HDIM / 256), 256>>>(base, out, b_x, b_l, b_r, b_px);
        } else {
            gemm_bf16<64, 64><<<dim3(1, GDIM / 64), 256, SMEM_SML>>>(
                rh, rl, hh + (size_t)base * FDIM, hl + (size_t)base * FDIM,
                (float*)pGT, 64, M);
            ew_small<<<dim3((M + 31) / 32, HDIM / 8), dim3(32, 8)>>>(
                base, M, out, b_x, b_l, b_r, b_px);
        }
    }
}

// round 9
// speedup vs baseline: 1.8951x; 1.2375x over previous
#include <cuda_runtime.h>
#include <cuda_bf16.h>
#include <math.h>
#include <stdint.h>

// ----------------------------- problem constants ----------------------------
#define NOBJ 2048
#define FDIM 2048
#define HDIM 1024
#define GDIM 6144
#define XG_LD 7168          // 6H gates + H px concatenated
#define EITER 192           // 3 products x (2048/32) k-chunks

// ----------------------------- device globals (no allocs) -------------------
__device__ __align__(1024) __nv_bfloat16 g_feat_hi[NOBJ * FDIM];
__device__ __align__(1024) __nv_bfloat16 g_feat_lo[NOBJ * FDIM];
__device__ __align__(1024) __nv_bfloat16 g_wb_hi[(size_t)XG_LD * FDIM];   // [w_x ; w_px]
__device__ __align__(1024) __nv_bfloat16 g_wb_lo[(size_t)XG_LD * FDIM];
__device__ __align__(1024) __nv_bfloat16 g_wrec_hi[(size_t)GDIM * FDIM];  // row n = [w_l[n]|w_r[n]]
__device__ __align__(1024) __nv_bfloat16 g_wrec_lo[(size_t)GDIM * FDIM];
__device__ __align__(1024) __nv_bfloat16 g_hrec_hi[NOBJ * FDIM];          // row p = [h(2p+1)|h(2p+2)]
__device__ __align__(1024) __nv_bfloat16 g_hrec_lo[NOBJ * FDIM];
__device__ float g_xgpx[(size_t)NOBJ * XG_LD];
__device__ float g_gates[512 * GDIM];
__device__ float g_gatesT[GDIM * 64];
__device__ float g_c[NOBJ * HDIM];

// ----------------------------- asm helpers ----------------------------------
__device__ __forceinline__ uint32_t smem_u32(const void* p) {
    uint32_t a;
    asm("{ .reg .u64 t; cvta.to.shared.u64 t, %1; cvt.u32.u64 %0, t; }" : "=r"(a) : "l"(p));
    return a;
}
__device__ __forceinline__ void cp16(uint32_t dst, const void* src, int srcsize) {
    asm volatile("cp.async.cg.shared.global [%0], [%1], 16, %2;"
                 :: "r"(dst), "l"(src), "r"(srcsize) : "memory");
}
#define CP_COMMIT() asm volatile("cp.async.commit_group;" ::: "memory")
#define CP_WAIT1() asm volatile("cp.async.wait_group 1;" ::: "memory")
#define CP_WAIT0() asm volatile("cp.async.wait_group 0;" ::: "memory")

__device__ __forceinline__ void ldsm_x4(uint32_t* r, uint32_t addr) {
    asm volatile("ldmatrix.sync.aligned.m8n8.x4.shared.b16 {%0,%1,%2,%3}, [%4];"
                 : "=r"(r[0]), "=r"(r[1]), "=r"(r[2]), "=r"(r[3]) : "r"(addr));
}
__device__ __forceinline__ void mma16816(float* c, const uint32_t* a, const uint32_t* b) {
    asm volatile(
        "mma.sync.aligned.m16n8k16.row.col.f32.bf16.bf16.f32 "
        "{%0,%1,%2,%3}, {%4,%5,%6,%7}, {%8,%9}, {%0,%1,%2,%3};"
        : "+f"(c[0]), "+f"(c[1]), "+f"(c[2]), "+f"(c[3])
        : "r"(a[0]), "r"(a[1]), "r"(a[2]), "r"(a[3]), "r"(b[0]), "r"(b[1]));
}

// ----------------------------- bf16 hi/lo TN GEMM ---------------------------
// C[M,N] = A[M,2048] @ B[N,2048]^T with 3-product hi/lo split:
//   phases: Ah*Bh, Al*Bh, Ah*Bl  (effective K = 6144)
// grid: (N/BN, M/BM). 256 threads, 2x4 warps. B rows >= nB zero-filled.
// BM in {32,64,128}, BN in {64,128} (NT even).
template <int BM, int BN>
__global__ __launch_bounds__(256, 1)
void gemm_bf16(const __nv_bfloat16* __restrict__ Ahi, const __nv_bfloat16* __restrict__ Alo,
               const __nv_bfloat16* __restrict__ Bhi, const __nv_bfloat16* __restrict__ Blo,
               float* __restrict__ C, int ldc, int nB) {
    constexpr int TH = 256;
    constexpr int WM = BM / 2, WN = BN / 4;
    constexpr int MT = WM / 16, NT = WN / 8;
    static_assert(MT >= 1 && (NT & 1) == 0, "layout");
    constexpr int PITCH = 80;                 // 64B row + 16B skew
    constexpr int SA = BM * PITCH, SB = BN * PITCH, STG = SA + SB;

    extern __shared__ char smem[];
    const uint32_t sbase = smem_u32(smem);
    const int tid = threadIdx.x, lane = tid & 31, wid = tid >> 5;
    const int wm = wid >> 2, wn = wid & 3;

    const int rowA0 = blockIdx.y * BM;
    const int rowB0 = blockIdx.x * BN;

    float acc[MT][NT][4];
#pragma unroll
    for (int i = 0; i < MT; i++)
#pragma unroll
        for (int j = 0; j < NT; j++)
#pragma unroll
            for (int t = 0; t < 4; t++) acc[i][j][t] = 0.0f;

    auto issue = [&](int e, int s) {
        const int p = e >> 6;
        const int k0 = (e & 63) * 32;
        const __nv_bfloat16* pa = (p == 1) ? Alo : Ahi;
        const __nv_bfloat16* pb = (p == 2) ? Blo : Bhi;
        const uint32_t sA = sbase + s * STG, sB = sA + SA;
#pragma unroll
        for (int idx = tid; idx < BM * 4; idx += TH) {
            int r = idx >> 2, sg = idx & 3;
            cp16(sA + r * PITCH + sg * 16,
                 pa + (size_t)(rowA0 + r) * FDIM + k0 + sg * 8, 16);
        }
#pragma unroll
        for (int idx = tid; idx < BN * 4; idx += TH) {
            int r = idx >> 2, sg = idx & 3;
            int gr = rowB0 + r;
            cp16(sB + r * PITCH + sg * 16,
                 pb + (size_t)gr * FDIM + k0 + sg * 8, gr < nB ? 16 : 0);
        }
    };

    issue(0, 0); CP_COMMIT();
    issue(1, 1); CP_COMMIT();

    for (int e = 0; e < EITER; e++) {
        if (e + 1 < EITER) CP_WAIT1(); else CP_WAIT0();
        __syncthreads();
        if (e + 2 < EITER) { issue(e + 2, (e + 2) % 3); CP_COMMIT(); }

        const int s = e % 3;
        const uint32_t sA = sbase + s * STG, sB = sA + SA;
        const uint32_t aBase = sA + (wm * WM + (lane & 15)) * PITCH + (lane >> 4) * 16;
        const uint32_t bBase = sB + (wn * WN + ((lane >> 4) * 8) + (lane & 7)) * PITCH +
                               ((lane >> 3) & 1) * 16;
#pragma unroll
        for (int kk = 0; kk < 2; kk++) {
            uint32_t a[MT][4];
#pragma unroll
            for (int i = 0; i < MT; i++)
                ldsm_x4(a[i], aBase + i * 16 * PITCH + kk * 32);
            uint32_t b[NT][2];
#pragma unroll
            for (int jj = 0; jj < NT / 2; jj++) {
                uint32_t r4[4];
                ldsm_x4(r4, bBase + jj * 16 * PITCH + kk * 32);
                b[2 * jj][0] = r4[0]; b[2 * jj][1] = r4[1];
                b[2 * jj + 1][0] = r4[2]; b[2 * jj + 1][1] = r4[3];
            }
#pragma unroll
            for (int i = 0; i < MT; i++)
#pragma unroll
                for (int j = 0; j < NT; j++) mma16816(acc[i][j], a[i], b[j]);
        }
    }

    // store
    const int mrow0 = blockIdx.y * BM + wm * WM + (lane >> 2);
    const int ncol0 = blockIdx.x * BN + wn * WN + (lane & 3) * 2;
#pragma unroll
    for (int i = 0; i < MT; i++)
#pragma unroll
        for (int j = 0; j < NT; j++) {
            int m = mrow0 + i * 16;
            int n = ncol0 + j * 8;
            *(float2*)(C + (size_t)m * ldc + n) = make_float2(acc[i][j][0], acc[i][j][1]);
            *(float2*)(C + (size_t)(m + 8) * ldc + n) = make_float2(acc[i][j][2], acc[i][j][3]);
        }
}

// ----------------------------- split fp32 -> bf16 hi/lo ---------------------
__global__ void split_k(const float* __restrict__ src, __nv_bfloat16* __restrict__ hi,
                        __nv_bfloat16* __restrict__ lo, int total, int scols,
                        int dld, int doff) {
    int idx = (blockIdx.x * 256 + threadIdx.x) * 8;
    if (idx >= total) return;
    float4 v0 = *(const float4*)(src + idx);
    float4 v1 = *(const float4*)(src + idx + 4);
    int r = idx / scols, c = idx - r * scols;
    size_t d = (size_t)r * dld + doff + c;
    float x[8] = {v0.x, v0.y, v0.z, v0.w, v1.x, v1.y, v1.z, v1.w};
    __nv_bfloat16 hbuf[8], lbuf[8];
#pragma unroll
    for (int t = 0; t < 8; t++) {
        __nv_bfloat16 h = __float2bfloat16(x[t]);
        hbuf[t] = h;
        lbuf[t] = __float2bfloat16(x[t] - __bfloat162float(h));
    }
    *(uint4*)(hi + d) = *(uint4*)hbuf;
    *(uint4*)(lo + d) = *(uint4*)lbuf;
}

__global__ void zero_hrec_k() {  // node 1023 has no right child
    int j = threadIdx.x;
    g_hrec_hi[1023 * FDIM + 1024 + j] = __float2bfloat16(0.0f);
    g_hrec_lo[1023 * FDIM + 1024 + j] = __float2bfloat16(0.0f);
}

// ----------------------------- fused LSTM elementwise ------------------------
__device__ __forceinline__ float sigf(float x) { return 1.0f / (1.0f + expf(-x)); }

__device__ __forceinline__ void lstm_core(const float* g, float cl, float cr, float px,
                                          float& c, float& hf) {
    float ig = sigf(g[0]), og = sigf(g[1]);
    float fl = sigf(g[2]), fr = sigf(g[3]);
    float u = tanhf(g[4]), rr = sigf(g[5]);
    c = ig * u + fl * cl + fr * cr;
    float h = og * tanhf(c);
    hf = rr * h + (1.0f - rr) * px;
}

__device__ __forceinline__ void write_node(int i, int j, float c, float hf,
                                           float* __restrict__ out) {
    g_c[(size_t)i * HDIM + j] = c;
    out[(size_t)i * HDIM + j] = hf;
    if (i > 0) {
        int p = (i - 1) >> 1;
        int off = (i & 1) ? 0 : 1024;  // odd index = left child
        __nv_bfloat16 h = __float2bfloat16(hf);
        g_hrec_hi[(size_t)p * FDIM + off + j] = h;
        g_hrec_lo[(size_t)p * FDIM + off + j] = __float2bfloat16(hf - __bfloat162float(h));
    }
}

__global__ void ew_leaf(float* __restrict__ out, const float* __restrict__ bx,
                        const float* __restrict__ bl, const float* __restrict__ br,
                        const float* __restrict__ bpx) {
    int i = 1024 + blockIdx.x;
    int j = blockIdx.y * 256 + threadIdx.x;
    const float* xr = g_xgpx + (size_t)i * XG_LD;
    float g[6];
#pragma unroll
    for (int s = 0; s < 6; s++) {
        int k = s * HDIM + j;
        g[s] = xr[k] + bx[k] + bl[k] + br[k];
    }
    float px = xr[GDIM + j] + bpx[j];
    float c, hf;
    lstm_core(g, 0.0f, 0.0f, px, c, hf);
    write_node(i, j, c, hf, out);
}

__global__ void ew_big(int base, float* __restrict__ out, const float* __restrict__ bx,
                       const float* __restrict__ bl, const float* __restrict__ br,
                       const float* __restrict__ bpx) {
    int r = blockIdx.x;
    int i = base + r;
    int j = blockIdx.y * 256 + threadIdx.x;
    const float* xr = g_xgpx + (size_t)i * XG_LD;
    const float* gr = g_gates + (size_t)r * GDIM;
    float g[6];
#pragma unroll
    for (int s = 0; s < 6; s++) {
        int k = s * HDIM + j;
        g[s] = xr[k] + gr[k] + bx[k] + bl[k] + br[k];
    }
    int lc = 2 * i + 1, rc = 2 * i + 2;
    float cl = (lc < NOBJ) ? g_c[(size_t)lc * HDIM + j] : 0.0f;
    float cr = (rc < NOBJ) ? g_c[(size_t)rc * HDIM + j] : 0.0f;
    float px = xr[GDIM + j] + bpx[j];
    float c, hf;
    lstm_core(g, cl, cr, px, c, hf);
    write_node(i, j, c, hf, out);
}

__global__ void ew_small(int base, int M, float* __restrict__ out,
                         const float* __restrict__ bx, const float* __restrict__ bl,
                         const float* __restrict__ br, const float* __restrict__ bpx) {
    int r = blockIdx.x * 32 + threadIdx.x;
    int j = blockIdx.y * 8 + threadIdx.y;
    if (r >= M) return;
    int i = base + r;
    const float* xr = g_xgpx + (size_t)i * XG_LD;
    float g[6];
#pragma unroll
    for (int s = 0; s < 6; s++) {
        int k = s * HDIM + j;
        g[s] = xr[k] + g_gatesT[(size_t)k * 64 + r] + bx[k] + bl[k] + br[k];
    }
    int lc = 2 * i + 1, rc = 2 * i + 2;
    float cl = (lc < NOBJ) ? g_c[(size_t)lc * HDIM + j] : 0.0f;
    float cr = (rc < NOBJ) ? g_c[(size_t)rc * HDIM + j] : 0.0f;
    float px = xr[GDIM + j] + bpx[j];
    float c, hf;
    lstm_core(g, cl, cr, px, c, hf);
    write_node(i, j, c, hf, out);
}

// ----------------------------- host launcher ---------------------------------
extern "C" void kernel_launch(void* const* d_in, const int* in_sizes, int n_in,
                              void* d_out, int out_size) {
    const float* features = (const float*)d_in[0];
    const float* w_x  = (const float*)d_in[1];
    const float* b_x  = (const float*)d_in[2];
    const float* w_l  = (const float*)d_in[3];
    const float* b_l  = (const float*)d_in[4];
    const float* w_r  = (const float*)d_in[5];
    const float* b_r  = (const float*)d_in[6];
    const float* w_px = (const float*)d_in[7];
    const float* b_px = (const float*)d_in[8];
    float* out = (float*)d_out;

    void *pFh, *pFl, *pWh, *pWl, *pRh, *pRl, *pHh, *pHl, *pXG, *pG, *pGT;
    cudaGetSymbolAddress(&pFh, g_feat_hi); cudaGetSymbolAddress(&pFl, g_feat_lo);
    cudaGetSymbolAddress(&pWh, g_wb_hi);   cudaGetSymbolAddress(&pWl, g_wb_lo);
    cudaGetSymbolAddress(&pRh, g_wrec_hi); cudaGetSymbolAddress(&pRl, g_wrec_lo);
    cudaGetSymbolAddress(&pHh, g_hrec_hi); cudaGetSymbolAddress(&pHl, g_hrec_lo);
    cudaGetSymbolAddress(&pXG, g_xgpx);
    cudaGetSymbolAddress(&pG, g_gates);
    cudaGetSymbolAddress(&pGT, g_gatesT);

    __nv_bfloat16* fh = (__nv_bfloat16*)pFh; __nv_bfloat16* fl = (__nv_bfloat16*)pFl;
    __nv_bfloat16* wh = (__nv_bfloat16*)pWh; __nv_bfloat16* wl = (__nv_bfloat16*)pWl;
    __nv_bfloat16* rh = (__nv_bfloat16*)pRh; __nv_bfloat16* rl = (__nv_bfloat16*)pRl;
    __nv_bfloat16* hh = (__nv_bfloat16*)pHh; __nv_bfloat16* hl = (__nv_bfloat16*)pHl;

    // smem: 3 stages x (BM+BN) x 80B
    const int SM_128_128 = 3 * (128 + 128) * 80;  // 61440
    const int SM_128_64  = 3 * (128 + 64) * 80;   // 46080
    const int SM_64_64   = 3 * (64 + 64) * 80;    // 30720
    const int SM_32_64   = 3 * (32 + 64) * 80;    // 23040
    cudaFuncSetAttribute(gemm_bf16<128, 128>, cudaFuncAttributeMaxDynamicSharedMemorySize, SM_128_128);
    cudaFuncSetAttribute(gemm_bf16<128, 64>,  cudaFuncAttributeMaxDynamicSharedMemorySize, SM_128_64);
    cudaFuncSetAttribute(gemm_bf16<64, 64>,   cudaFuncAttributeMaxDynamicSharedMemorySize, SM_64_64);
    cudaFuncSetAttribute(gemm_bf16<32, 64>,   cudaFuncAttributeMaxDynamicSharedMemorySize, SM_32_64);

    zero_hrec_k<<<1, 1024>>>();
    split_k<<<(NOBJ * FDIM / 8 + 255) / 256, 256>>>(features, fh, fl, NOBJ * FDIM, FDIM, FDIM, 0);
    split_k<<<(GDIM * FDIM / 8 + 255) / 256, 256>>>(w_x, wh, wl, GDIM * FDIM, FDIM, FDIM, 0);
    split_k<<<(HDIM * FDIM / 8 + 255) / 256, 256>>>(w_px, wh + (size_t)GDIM * FDIM,
                                                    wl + (size_t)GDIM * FDIM,
                                                    HDIM * FDIM, FDIM, FDIM, 0);
    split_k<<<(GDIM * HDIM / 8 + 255) / 256, 256>>>(w_l, rh, rl, GDIM * HDIM, HDIM, FDIM, 0);
    split_k<<<(GDIM * HDIM / 8 + 255) / 256, 256>>>(w_r, rh, rl, GDIM * HDIM, HDIM, FDIM, 1024);

    // fused input projections: [2048,7168] = features @ [w_x;w_px]^T
    gemm_bf16<128, 128><<<dim3(XG_LD / 128, NOBJ / 128), 256, SM_128_128>>>(
        fh, fl, wh, wl, (float*)pXG, XG_LD, XG_LD);

    // leaves: nodes 1024..2047
    ew_leaf<<<dim3(1024, HDIM / 256), 256>>>(out, b_x, b_l, b_r, b_px);

    // node 1023 (single internal node at level 10); transposed roles, BM over GDIM
    gemm_bf16<32, 64><<<dim3(1, GDIM / 32), 256, SM_32_64>>>(
        rh, rl, hh + (size_t)1023 * FDIM, hl + (size_t)1023 * FDIM, (float*)pGT, 64, 1);
    ew_small<<<dim3(1, HDIM / 8), dim3(32, 8)>>>(1023, 1, out, b_x, b_l, b_r, b_px);

    // levels 9..0
    for (int l = 9; l >= 0; l--) {
        int base = (1 << l) - 1;
        int M = 1 << l;
        if (M >= 128) {
            const __nv_bfloat16* ah = hh + (size_t)base * FDIM;
            const __nv_bfloat16* al = hl + (size_t)base * FDIM;
            if (M == 512) {
                gemm_bf16<128, 64><<<dim3(GDIM / 64, M / 128), 256, SM_128_64>>>(
                    ah, al, rh, rl, (float*)pG, GDIM, GDIM);
            } else if (M == 256) {
                gemm_bf16<64, 64><<<dim3(GDIM / 64, M / 64), 256, SM_64_64>>>(
                    ah, al, rh, rl, (float*)pG, GDIM, GDIM);
            } else {  // M == 128
                gemm_bf16<32, 64><<<dim3(GDIM / 64, M / 32), 256, SM_32_64>>>(
                    ah, al, rh, rl, (float*)pG, GDIM, GDIM);
            }
            ew_big<<<dim3(M, HDIM / 256), 256>>>(base, out, b_x, b_l, b_r, b_px);
        } else {
            gemm_bf16<32, 64><<<dim3(1, GDIM / 32), 256, SM_32_64>>>(
                rh, rl, hh + (size_t)base * FDIM, hl + (size_t)base * FDIM,
                (float*)pGT, 64, M);
            ew_small<<<dim3((M + 31) / 32, HDIM / 8), dim3(32, 8)>>>(
                base, M, out, b_x, b_l, b_r, b_px);
        }
    }
}